// round 11
// baseline (speedup 1.0000x reference)
#include <cuda_runtime.h>

// Inputs (metadata order):
//   d_in[0] t_inters : float32 [B, N, 2]   (B=4096, N=128)
//   d_in[1] weights  : float32 [B, N]
//   d_in[2] t_near   : float32 [B, 1]
//   d_in[3] t_far    : float32 [B, 1]
// Output: float32 [B]
//
// Single-scan sorted-u identity:
//   inter = 2*sum_i w_i u_i (2*W_{<i} + w_i)  -  2*W_tot * sum_i w_i u_i
//   intra = (1/3) * sum_i w_i^2 * ds_i
// Only w is scanned. W_tot comes free from the scan (segment lane 15) via a
// single broadcast shuffle; -W_tot*Su and intra/6 are folded per-lane into A,
// so the epilogue is ONE 4-step width-16 butterfly:
//   out = 2 * sum_lanes( A + C/6 - W_tot*Su )
// SHFL chain: 4 (scan) + 1 (broadcast) + 4 (butterfly) = 9 total.
//
// Layout: 2 rows per warp (lanes [0,16) -> row0, [16,32) -> row1),
// 8 elements per lane, 512 threads x 128 CTAs (single wave).
//
// FINAL (session verdict, 10 rounds): variants spanning MLP 3-12,
// occ 12-72%, grid 128-4096, LDG vs TMA bulk, 30 vs 9 shuffles all measure
// 6.62-8.70us wall with DRAM <=15% busy; identical binaries differ by up to
// 2us across runs. The benchmark is bound by a ~6.6us launch+cold-DRAM floor
// plus DVFS noise, not by any SM-side resource. Traffic is irreducible
// (shared interval boundaries are interleaved, so sector-granularity DRAM
// bytes are fixed at 6.3MB). This kernel is the best-measured configuration
// (6.624us wall, 5.376us ncu internal, rel_err 1.5e-7).

__global__ __launch_bounds__(512, 2)
void distor_value_kernel(const float* __restrict__ t_inters,
                         const float* __restrict__ weights,
                         const float* __restrict__ t_near,
                         const float* __restrict__ t_far,
                         float* __restrict__ out,
                         int B) {
    const int warp = (int)((blockIdx.x * blockDim.x + threadIdx.x) >> 5);
    const int lane = (int)(threadIdx.x & 31);
    const int sub  = lane & 15;
    int row        = warp * 2 + (lane >> 4);
    if (warp * 2 >= B) return;
    const bool valid = (row < B);
    if (!valid) row = B - 1;

    // Scalars first: inv/nh resolve while the vector loads are in flight.
    const float nearv = t_near[row];
    const float farv  = t_far[row];

    const float4* ti = reinterpret_cast<const float4*>(t_inters) + (size_t)row * 64 + sub * 4;
    const float4  a0 = ti[0];
    const float4  a1 = ti[1];
    const float4  a2 = ti[2];
    const float4  a3 = ti[3];
    const float4* wp = reinterpret_cast<const float4*>(weights) + (size_t)row * 32 + sub * 2;
    const float4  w0 = wp[0];
    const float4  w1 = wp[1];

    const float inv = 1.0f / (farv - nearv);
    const float nh  = nearv * inv;

    float u[8], dsv[8], wv[8];
    u[0] = fmaf((a0.x + a0.y), 0.5f * inv, -nh);  dsv[0] = (a0.y - a0.x) * inv;
    u[1] = fmaf((a0.z + a0.w), 0.5f * inv, -nh);  dsv[1] = (a0.w - a0.z) * inv;
    u[2] = fmaf((a1.x + a1.y), 0.5f * inv, -nh);  dsv[2] = (a1.y - a1.x) * inv;
    u[3] = fmaf((a1.z + a1.w), 0.5f * inv, -nh);  dsv[3] = (a1.w - a1.z) * inv;
    u[4] = fmaf((a2.x + a2.y), 0.5f * inv, -nh);  dsv[4] = (a2.y - a2.x) * inv;
    u[5] = fmaf((a2.z + a2.w), 0.5f * inv, -nh);  dsv[5] = (a2.w - a2.z) * inv;
    u[6] = fmaf((a3.x + a3.y), 0.5f * inv, -nh);  dsv[6] = (a3.y - a3.x) * inv;
    u[7] = fmaf((a3.z + a3.w), 0.5f * inv, -nh);  dsv[7] = (a3.w - a3.z) * inv;
    wv[0] = w0.x; wv[1] = w0.y; wv[2] = w0.z; wv[3] = w0.w;
    wv[4] = w1.x; wv[5] = w1.y; wv[6] = w1.z; wv[7] = w1.w;

    // In-lane exclusive prefix of w (independent of the warp scan).
    float pw[8];
    pw[0] = 0.0f;
    #pragma unroll
    for (int k = 1; k < 8; k++) pw[k] = pw[k - 1] + wv[k - 1];
    const float Wloc = pw[7] + wv[7];

    float wu[8];
    #pragma unroll
    for (int k = 0; k < 8; k++) wu[k] = wv[k] * u[k];

    // Width-16 segmented inclusive scan of lane w-totals (4 steps).
    float Winc = Wloc;
    #pragma unroll
    for (int off = 1; off < 16; off <<= 1) {
        float wUp = __shfl_up_sync(0xFFFFFFFFu, Winc, off, 16);
        if (sub >= off) Winc += wUp;
    }
    const float Wr = Winc - Wloc;    // exclusive prefix of w at lane start
    // Row total = segment lane 15's inclusive value (one broadcast shuffle).
    const float Wt = __shfl_sync(0xFFFFFFFFu, Winc, 15, 16);

    // Per-lane accumulators; everything folds into A before the reduction.
    float A = 0.0f, Su = 0.0f, C = 0.0f;
    #pragma unroll
    for (int k = 0; k < 8; k++) {
        A  = fmaf(wu[k], fmaf(2.0f, Wr + pw[k], wv[k]), A);
        Su += wu[k];
        C  = fmaf(wv[k] * wv[k], dsv[k], C);
    }
    A = fmaf(C, (1.0f / 6.0f), A);   // + intra/6
    A = fmaf(-Wt, Su, A);            // - W_tot * (lane's share of sum wu)

    // Single width-16 butterfly reduction (4 steps).
    #pragma unroll
    for (int off = 8; off > 0; off >>= 1)
        A += __shfl_xor_sync(0xFFFFFFFFu, A, off, 16);

    if (valid && sub == 0)
        out[row] = 2.0f * A;
}

extern "C" void kernel_launch(void* const* d_in, const int* in_sizes, int n_in,
                              void* d_out, int out_size) {
    const float* t_inters = (const float*)d_in[0];
    const float* weights  = (const float*)d_in[1];
    const float* t_near   = (const float*)d_in[2];
    const float* t_far    = (const float*)d_in[3];
    float* out = (float*)d_out;

    const int B = out_size;                       // 4096 rows, 2 rows per warp
    const int warps   = (B + 1) / 2;              // 2048
    const int threads = 512;                      // 16 warps per CTA
    const int blocks  = (warps * 32 + threads - 1) / threads;  // 128 CTAs
    distor_value_kernel<<<blocks, threads>>>(t_inters, weights, t_near, t_far, out, B);
}

// round 12
// speedup vs baseline: 1.0386x; 1.0386x over previous
#include <cuda_runtime.h>

// Inputs (metadata order):
//   d_in[0] t_inters : float32 [B, N, 2]   (B=4096, N=128)
//   d_in[1] weights  : float32 [B, N]
//   d_in[2] t_near   : float32 [B, 1]
//   d_in[3] t_far    : float32 [B, 1]
// Output: float32 [B]
//
// Single-scan sorted-u identity:
//   inter = 2*sum_i w_i u_i (2*W_{<i} + w_i)  -  2*W_tot * sum_i w_i u_i
//   intra = (1/3) * sum_i w_i^2 * ds_i
// Only w is scanned. W_tot comes free from the scan (segment lane 15) via a
// single broadcast shuffle; -W_tot*Su and intra/6 are folded per-lane into A,
// so the epilogue is ONE 4-step width-16 butterfly:
//   out = 2 * sum_lanes( A + C/6 - W_tot*Su )
// SHFL chain: 4 (scan) + 1 (broadcast) + 4 (butterfly) = 9 total.
//
// Layout: 2 rows per warp (lanes [0,16) -> row0, [16,32) -> row1),
// 8 elements per lane, 512 threads x 128 CTAs (single wave).
//
// FINAL (session verdict, 11 rounds): variants spanning MLP 3-12,
// occ 12-72%, grid 128-4096, LDG vs TMA bulk, 30 vs 9 shuffles all measure
// 6.62-8.70us wall with DRAM <=15% busy; identical binaries differ by up to
// 2us across runs. The benchmark is bound by a ~6.6us launch+cold-DRAM floor
// plus DVFS noise, not by any SM-side resource. Traffic is irreducible
// (shared interval boundaries are interleaved, so sector-granularity DRAM
// bytes are fixed at 6.3MB). This kernel is the best-measured configuration
// (6.624us wall best draw, 5.376us ncu internal best, rel_err 1.5e-7).

__global__ __launch_bounds__(512, 2)
void distor_value_kernel(const float* __restrict__ t_inters,
                         const float* __restrict__ weights,
                         const float* __restrict__ t_near,
                         const float* __restrict__ t_far,
                         float* __restrict__ out,
                         int B) {
    const int warp = (int)((blockIdx.x * blockDim.x + threadIdx.x) >> 5);
    const int lane = (int)(threadIdx.x & 31);
    const int sub  = lane & 15;
    int row        = warp * 2 + (lane >> 4);
    if (warp * 2 >= B) return;
    const bool valid = (row < B);
    if (!valid) row = B - 1;

    // Scalars first: inv/nh resolve while the vector loads are in flight.
    const float nearv = t_near[row];
    const float farv  = t_far[row];

    const float4* ti = reinterpret_cast<const float4*>(t_inters) + (size_t)row * 64 + sub * 4;
    const float4  a0 = ti[0];
    const float4  a1 = ti[1];
    const float4  a2 = ti[2];
    const float4  a3 = ti[3];
    const float4* wp = reinterpret_cast<const float4*>(weights) + (size_t)row * 32 + sub * 2;
    const float4  w0 = wp[0];
    const float4  w1 = wp[1];

    const float inv = 1.0f / (farv - nearv);
    const float nh  = nearv * inv;

    float u[8], dsv[8], wv[8];
    u[0] = fmaf((a0.x + a0.y), 0.5f * inv, -nh);  dsv[0] = (a0.y - a0.x) * inv;
    u[1] = fmaf((a0.z + a0.w), 0.5f * inv, -nh);  dsv[1] = (a0.w - a0.z) * inv;
    u[2] = fmaf((a1.x + a1.y), 0.5f * inv, -nh);  dsv[2] = (a1.y - a1.x) * inv;
    u[3] = fmaf((a1.z + a1.w), 0.5f * inv, -nh);  dsv[3] = (a1.w - a1.z) * inv;
    u[4] = fmaf((a2.x + a2.y), 0.5f * inv, -nh);  dsv[4] = (a2.y - a2.x) * inv;
    u[5] = fmaf((a2.z + a2.w), 0.5f * inv, -nh);  dsv[5] = (a2.w - a2.z) * inv;
    u[6] = fmaf((a3.x + a3.y), 0.5f * inv, -nh);  dsv[6] = (a3.y - a3.x) * inv;
    u[7] = fmaf((a3.z + a3.w), 0.5f * inv, -nh);  dsv[7] = (a3.w - a3.z) * inv;
    wv[0] = w0.x; wv[1] = w0.y; wv[2] = w0.z; wv[3] = w0.w;
    wv[4] = w1.x; wv[5] = w1.y; wv[6] = w1.z; wv[7] = w1.w;

    // In-lane exclusive prefix of w (independent of the warp scan).
    float pw[8];
    pw[0] = 0.0f;
    #pragma unroll
    for (int k = 1; k < 8; k++) pw[k] = pw[k - 1] + wv[k - 1];
    const float Wloc = pw[7] + wv[7];

    float wu[8];
    #pragma unroll
    for (int k = 0; k < 8; k++) wu[k] = wv[k] * u[k];

    // Width-16 segmented inclusive scan of lane w-totals (4 steps).
    float Winc = Wloc;
    #pragma unroll
    for (int off = 1; off < 16; off <<= 1) {
        float wUp = __shfl_up_sync(0xFFFFFFFFu, Winc, off, 16);
        if (sub >= off) Winc += wUp;
    }
    const float Wr = Winc - Wloc;    // exclusive prefix of w at lane start
    // Row total = segment lane 15's inclusive value (one broadcast shuffle).
    const float Wt = __shfl_sync(0xFFFFFFFFu, Winc, 15, 16);

    // Per-lane accumulators; everything folds into A before the reduction.
    float A = 0.0f, Su = 0.0f, C = 0.0f;
    #pragma unroll
    for (int k = 0; k < 8; k++) {
        A  = fmaf(wu[k], fmaf(2.0f, Wr + pw[k], wv[k]), A);
        Su += wu[k];
        C  = fmaf(wv[k] * wv[k], dsv[k], C);
    }
    A = fmaf(C, (1.0f / 6.0f), A);   // + intra/6
    A = fmaf(-Wt, Su, A);            // - W_tot * (lane's share of sum wu)

    // Single width-16 butterfly reduction (4 steps).
    #pragma unroll
    for (int off = 8; off > 0; off >>= 1)
        A += __shfl_xor_sync(0xFFFFFFFFu, A, off, 16);

    if (valid && sub == 0)
        out[row] = 2.0f * A;
}

extern "C" void kernel_launch(void* const* d_in, const int* in_sizes, int n_in,
                              void* d_out, int out_size) {
    const float* t_inters = (const float*)d_in[0];
    const float* weights  = (const float*)d_in[1];
    const float* t_near   = (const float*)d_in[2];
    const float* t_far    = (const float*)d_in[3];
    float* out = (float*)d_out;

    const int B = out_size;                       // 4096 rows, 2 rows per warp
    const int warps   = (B + 1) / 2;              // 2048
    const int threads = 512;                      // 16 warps per CTA
    const int blocks  = (warps * 32 + threads - 1) / threads;  // 128 CTAs
    distor_value_kernel<<<blocks, threads>>>(t_inters, weights, t_near, t_far, out, B);
}